// round 7
// baseline (speedup 1.0000x reference)
#include <cuda_runtime.h>
#include <math.h>

#define NN_ 1536
#define DD_ 768
#define HH_ 64
#define PLANE (NN_ * NN_)
#define KSPLIT 12

// Scratch (fully overwritten every launch -> graph-replay safe)
__device__ float g_part[KSPLIT * NN_ * 128]; // k-split partials of E@[W1a|W1b]
__device__ float g_A[NN_ * HH_];             // ha - g
__device__ float g_B[NN_ * HH_];             // hb + g + b1
__device__ float g_pv[NN_ * 6];              // pos(3), vel(3)

// ---------------------------------------------------------------------------
// Kernel 1: partial GEMM, double-buffered + register prefetch.
// grid (24, KSPLIT), 256 threads. Block (rb, ks): rows rb*64..+63,
// k-chunk ks*64..+63, 128 output cols (0..63 = W1a, 64..127 = W1b).
// Per thread: 8 rows x 4 cols. E tile stored k-major (transposed).
// One __syncthreads per k-tile: STS goes to the opposite buffer.
// ---------------------------------------------------------------------------
__global__ __launch_bounds__(256) void gemm_partial_kernel(
    const float* __restrict__ E, const float* __restrict__ W1)
{
    __shared__ __align__(16) float sET[2][16 * 68];  // [buf][kk][row]
    __shared__ __align__(16) float sW[2][16 * 128];  // [buf][kk][h2]

    const int t    = threadIdx.x;
    const int rb   = blockIdx.x;
    const int ks   = blockIdx.y;
    const int lane = t & 31;   // col group: cols lane*4..+3
    const int wrp  = t >> 5;   // row group: rows wrp*8..+7

    const int erow = t >> 2, ec4 = t & 3;          // E: one float4 per thread
    const int wkk0 = t >> 5, wc0 = t & 31;         // W: two float4 per thread

    const float4* E4  = reinterpret_cast<const float4*>(E);
    const float4* W4g = reinterpret_cast<const float4*>(W1);

    float4 acc[8];
#pragma unroll
    for (int r = 0; r < 8; ++r) acc[r] = make_float4(0.f, 0.f, 0.f, 0.f);

    // prologue: prefetch tile 0 into registers, store to buf 0
    int kbase = ks * 64;
    float4 pe  = E4[((rb * 64 + erow) * DD_ + kbase) / 4 + ec4];
    float4 pw0 = (wc0 < 16) ? W4g[((kbase + wkk0) * 64) / 4 + wc0]
                            : W4g[((DD_ + kbase + wkk0) * 64) / 4 + (wc0 - 16)];
    float4 pw1 = (wc0 < 16) ? W4g[((kbase + wkk0 + 8) * 64) / 4 + wc0]
                            : W4g[((DD_ + kbase + wkk0 + 8) * 64) / 4 + (wc0 - 16)];

    sET[0][(ec4 * 4 + 0) * 68 + erow] = pe.x;
    sET[0][(ec4 * 4 + 1) * 68 + erow] = pe.y;
    sET[0][(ec4 * 4 + 2) * 68 + erow] = pe.z;
    sET[0][(ec4 * 4 + 3) * 68 + erow] = pe.w;
    reinterpret_cast<float4*>(sW[0])[wkk0 * 32 + wc0]       = pw0;
    reinterpret_cast<float4*>(sW[0])[(wkk0 + 8) * 32 + wc0] = pw1;
    __syncthreads();

#pragma unroll
    for (int kt = 0; kt < 4; ++kt) {
        const int cur = kt & 1;
        const int nxt = cur ^ 1;

        // prefetch next tile (overlaps with compute below)
        if (kt < 3) {
            const int kb = ks * 64 + (kt + 1) * 16;
            pe  = E4[((rb * 64 + erow) * DD_ + kb) / 4 + ec4];
            pw0 = (wc0 < 16) ? W4g[((kb + wkk0) * 64) / 4 + wc0]
                             : W4g[((DD_ + kb + wkk0) * 64) / 4 + (wc0 - 16)];
            pw1 = (wc0 < 16) ? W4g[((kb + wkk0 + 8) * 64) / 4 + wc0]
                             : W4g[((DD_ + kb + wkk0 + 8) * 64) / 4 + (wc0 - 16)];
        }

        const float4* sET4 = reinterpret_cast<const float4*>(sET[cur]);
        const float4* sW4  = reinterpret_cast<const float4*>(sW[cur]);
#pragma unroll
        for (int kk = 0; kk < 16; ++kk) {
            float4 w  = sW4[kk * 32 + lane];
            float4 e0 = sET4[kk * 17 + wrp * 2 + 0];  // rows wrp*8..+3
            float4 e1 = sET4[kk * 17 + wrp * 2 + 1];  // rows wrp*8+4..+7
            const float ev[8] = {e0.x, e0.y, e0.z, e0.w, e1.x, e1.y, e1.z, e1.w};
#pragma unroll
            for (int r = 0; r < 8; ++r) {
                acc[r].x = fmaf(ev[r], w.x, acc[r].x);
                acc[r].y = fmaf(ev[r], w.y, acc[r].y);
                acc[r].z = fmaf(ev[r], w.z, acc[r].z);
                acc[r].w = fmaf(ev[r], w.w, acc[r].w);
            }
        }

        // store prefetched tile into the other buffer, then single sync
        if (kt < 3) {
            sET[nxt][(ec4 * 4 + 0) * 68 + erow] = pe.x;
            sET[nxt][(ec4 * 4 + 1) * 68 + erow] = pe.y;
            sET[nxt][(ec4 * 4 + 2) * 68 + erow] = pe.z;
            sET[nxt][(ec4 * 4 + 3) * 68 + erow] = pe.w;
            reinterpret_cast<float4*>(sW[nxt])[wkk0 * 32 + wc0]       = pw0;
            reinterpret_cast<float4*>(sW[nxt])[(wkk0 + 8) * 32 + wc0] = pw1;
            __syncthreads();
        }
    }

    float4* dst = reinterpret_cast<float4*>(g_part) + (size_t)ks * (NN_ * 32);
    const int rbase = rb * 64 + wrp * 8;
#pragma unroll
    for (int r = 0; r < 8; ++r)
        dst[(rbase + r) * 32 + lane] = acc[r];
}

// ---------------------------------------------------------------------------
// Kernel 2: reduce partials + fold geometry. grid 96, block (16,16).
// Thread (h4, i_local): float4 over the h dimension, 24 independent LDG.128.
// ---------------------------------------------------------------------------
__global__ __launch_bounds__(256) void fold_kernel(
    const float* __restrict__ pos, const float* __restrict__ prev,
    const float* __restrict__ W1, const float* __restrict__ b1)
{
    const int h4 = threadIdx.x;                     // 0..15
    const int i  = blockIdx.x * 16 + threadIdx.y;

    const float4* P4 = reinterpret_cast<const float4*>(g_part);
    float4 sa = make_float4(0.f, 0.f, 0.f, 0.f);
    float4 sb = make_float4(0.f, 0.f, 0.f, 0.f);
#pragma unroll
    for (int s = 0; s < KSPLIT; ++s) {
        size_t base = ((size_t)s * (NN_ * 128) + (size_t)i * 128) >> 2;
        float4 va = P4[base + h4];
        float4 vb = P4[base + 16 + h4];
        sa.x += va.x; sa.y += va.y; sa.z += va.z; sa.w += va.w;
        sb.x += vb.x; sb.y += vb.y; sb.z += vb.z; sb.w += vb.w;
    }

    float px = pos[i * 3 + 0], py = pos[i * 3 + 1], pz = pos[i * 3 + 2];
    float vx = px - prev[i * 3 + 0];
    float vy = py - prev[i * 3 + 1];
    float vz = pz - prev[i * 3 + 2];

    const float4* Ws4 = reinterpret_cast<const float4*>(W1 + 2 * DD_ * 64);
    float4 w0 = Ws4[0 * 16 + h4], w1 = Ws4[1 * 16 + h4], w2 = Ws4[2 * 16 + h4];
    float4 w4 = Ws4[4 * 16 + h4], w5 = Ws4[5 * 16 + h4], w6 = Ws4[6 * 16 + h4];
    float4 w7 = Ws4[7 * 16 + h4];
    float4 b14 = reinterpret_cast<const float4*>(b1)[h4];

    float4 g;
    g.x = px*w0.x + py*w1.x + pz*w2.x + vx*w4.x + vy*w5.x + vz*w6.x + py*w7.x;
    g.y = px*w0.y + py*w1.y + pz*w2.y + vx*w4.y + vy*w5.y + vz*w6.y + py*w7.y;
    g.z = px*w0.z + py*w1.z + pz*w2.z + vx*w4.z + vy*w5.z + vz*w6.z + py*w7.z;
    g.w = px*w0.w + py*w1.w + pz*w2.w + vx*w4.w + vy*w5.w + vz*w6.w + py*w7.w;

    float4 outA = make_float4(sa.x - g.x, sa.y - g.y, sa.z - g.z, sa.w - g.w);
    float4 outB = make_float4(sb.x + g.x + b14.x, sb.y + g.y + b14.y,
                              sb.z + g.z + b14.z, sb.w + g.w + b14.w);
    reinterpret_cast<float4*>(g_A)[i * 16 + h4] = outA;
    reinterpret_cast<float4*>(g_B)[i * 16 + h4] = outB;

    if (h4 == 0) {
        g_pv[i * 6 + 0] = px; g_pv[i * 6 + 1] = py; g_pv[i * 6 + 2] = pz;
        g_pv[i * 6 + 3] = vx; g_pv[i * 6 + 4] = vy; g_pv[i * 6 + 5] = vz;
    }
}

// ---------------------------------------------------------------------------
// Kernel 3: pairwise. grid (48, 48), block (16, 16). Each thread: 2x2 strided
// micro-tile i in {ty, ty+16}, j in {tx, tx+16}.
// Logits as softmax-invariant differences: delta_k = l_k - l_0 using
// W2d[h][k] = W2[h][k+1] - W2[h][0]  (3 accumulators per pair, not 4).
// ---------------------------------------------------------------------------
__global__ __launch_bounds__(256) void pair_kernel(
    const float* __restrict__ W1, const float* __restrict__ W2,
    const float* __restrict__ b2, float* __restrict__ out)
{
    __shared__ __align__(16) float sA[32 * 68];   // rows padded to 68 floats
    __shared__ __align__(16) float sB[32 * 68];
    __shared__ __align__(16) float4 sW2d[64];     // (d1,d2,d3,0) per h
    __shared__ __align__(16) float sW3[64];
    __shared__ float sPVi[32 * 6];
    __shared__ float sPVj[32 * 6];

    const int tx = threadIdx.x, ty = threadIdx.y;
    const int t  = ty * 16 + tx;
    const int i0 = blockIdx.y * 32;
    const int j0 = blockIdx.x * 32;

    for (int idx = t; idx < 512; idx += 256) {
        int r = idx >> 4, c = idx & 15;
        reinterpret_cast<float4*>(sA)[r * 17 + c] =
            reinterpret_cast<const float4*>(g_A)[(i0 + r) * 16 + c];
        reinterpret_cast<float4*>(sB)[r * 17 + c] =
            reinterpret_cast<const float4*>(g_B)[(j0 + r) * 16 + c];
    }
    if (t < 64) {
        float w0 = W2[t * 4 + 0];
        sW2d[t] = make_float4(W2[t * 4 + 1] - w0, W2[t * 4 + 2] - w0,
                              W2[t * 4 + 3] - w0, 0.f);
        sW3[t] = W1[(2 * DD_ + 3) * 64 + t];  // w3 = W1s row 3 (distance)
    }
    for (int idx = t; idx < 192; idx += 256) {
        sPVi[idx] = g_pv[i0 * 6 + idx];
        sPVj[idx] = g_pv[j0 * 6 + idx];
    }
    __syncthreads();

    // geometry for the 4 pairs
    float dist[4], clos[4], vdif[4];
#pragma unroll
    for (int p = 0; p < 2; ++p) {
        int ri = ty + p * 16;
        float pix = sPVi[ri * 6 + 0], piy = sPVi[ri * 6 + 1], piz = sPVi[ri * 6 + 2];
        float vix = sPVi[ri * 6 + 3], viy = sPVi[ri * 6 + 4], viz = sPVi[ri * 6 + 5];
#pragma unroll
        for (int q = 0; q < 2; ++q) {
            int rj = tx + q * 16;
            float rpx = sPVj[rj * 6 + 0] - pix;
            float rpy = sPVj[rj * 6 + 1] - piy;
            float rpz = sPVj[rj * 6 + 2] - piz;
            float rvx = sPVj[rj * 6 + 3] - vix;
            float rvy = sPVj[rj * 6 + 4] - viy;
            float rvz = sPVj[rj * 6 + 5] - viz;
            float d = sqrtf(rpx * rpx + rpy * rpy + rpz * rpz);
            float dot = rpx * rvx + rpy * rvy + rpz * rvz;
            int pq = p * 2 + q;
            dist[pq] = d;
            clos[pq] = -dot / fmaxf(d, 1e-6f);
            vdif[pq] = rpy;
        }
    }

    float acc1[4] = {0.f, 0.f, 0.f, 0.f};
    float acc2[4] = {0.f, 0.f, 0.f, 0.f};
    float acc3[4] = {0.f, 0.f, 0.f, 0.f};

    const float4* A4  = reinterpret_cast<const float4*>(sA);
    const float4* B4  = reinterpret_cast<const float4*>(sB);
    const float4* W34 = reinterpret_cast<const float4*>(sW3);

#pragma unroll 4
    for (int h4 = 0; h4 < 16; ++h4) {
        float4 af[2], bf[2];
        af[0] = A4[ty * 17 + h4];
        af[1] = A4[(ty + 16) * 17 + h4];
        bf[0] = B4[tx * 17 + h4];
        bf[1] = B4[(tx + 16) * 17 + h4];
        float4 w3v = W34[h4];
        float4 wd0 = sW2d[h4 * 4 + 0];
        float4 wd1 = sW2d[h4 * 4 + 1];
        float4 wd2 = sW2d[h4 * 4 + 2];
        float4 wd3 = sW2d[h4 * 4 + 3];

        const float aw[2][4] = {{af[0].x, af[0].y, af[0].z, af[0].w},
                                {af[1].x, af[1].y, af[1].z, af[1].w}};
        const float bw[2][4] = {{bf[0].x, bf[0].y, bf[0].z, bf[0].w},
                                {bf[1].x, bf[1].y, bf[1].z, bf[1].w}};
        const float w3a[4] = {w3v.x, w3v.y, w3v.z, w3v.w};
        const float4 wda[4] = {wd0, wd1, wd2, wd3};

#pragma unroll
        for (int hh = 0; hh < 4; ++hh) {
            const float w3h = w3a[hh];
            const float4 wd = wda[hh];
#pragma unroll
            for (int p = 0; p < 2; ++p) {
#pragma unroll
                for (int q = 0; q < 2; ++q) {
                    const int pq = p * 2 + q;
                    float tt = fmaf(dist[pq], w3h, aw[p][hh] + bw[q][hh]);
                    float r  = fmaxf(tt, 0.f);
                    acc1[pq] = fmaf(r, wd.x, acc1[pq]);
                    acc2[pq] = fmaf(r, wd.y, acc2[pq]);
                    acc3[pq] = fmaf(r, wd.z, acc3[pq]);
                }
            }
        }
    }

    const float db1 = __ldg(&b2[1]) - __ldg(&b2[0]);
    const float db2 = __ldg(&b2[2]) - __ldg(&b2[0]);
    const float db3 = __ldg(&b2[3]) - __ldg(&b2[0]);

#pragma unroll
    for (int p = 0; p < 2; ++p) {
#pragma unroll
        for (int q = 0; q < 2; ++q) {
            const int pq = p * 2 + q;
            float d1 = acc1[pq] + db1;
            float d2 = acc2[pq] + db2;
            float d3 = acc3[pq] + db3;
            float m = fmaxf(fmaxf(0.f, d1), fmaxf(d2, d3));
            float sum = __expf(0.f - m) + __expf(d1 - m)
                      + __expf(d2 - m) + __expf(d3 - m);
            float conf = __fdividef(1.0f, sum);
            int best = 0; float bm = 0.f;
            if (d1 > bm) { bm = d1; best = 1; }
            if (d2 > bm) { bm = d2; best = 2; }
            if (d3 > bm) { bm = d3; best = 3; }

            float d = dist[pq], c = clos[pq], v = vdif[pq];
            bool near  = d < 0.25f;
            bool appr  = !near && (c > 0.05f);
            bool flee  = !near && !appr && (c < -0.05f);
            bool above = !near && !appr && !flee && (fabsf(v) > 0.3f) && (d < 0.5f);

            int rt = near ? 0 : (appr ? 1 : (flee ? 2 : (above ? 3 : best)));
            float co = conf;
            if (near)              co = fmaxf(co, 0.8f);
            else if (appr || flee) co = fmaxf(co, 0.6f);
            else if (above)        co = fmaxf(co, 0.5f);

            int ig = i0 + ty + p * 16;
            int jg = j0 + tx + q * 16;
            size_t off = (size_t)ig * NN_ + jg;
            out[off]             = (float)rt;
            out[PLANE + off]     = co;
            out[2 * PLANE + off] = (jg > ig && co > 0.3f) ? 1.0f : 0.0f;
        }
    }
}

extern "C" void kernel_launch(void* const* d_in, const int* in_sizes, int n_in,
                              void* d_out, int out_size)
{
    const float* E    = (const float*)d_in[0];
    const float* pos  = (const float*)d_in[1];
    const float* prev = (const float*)d_in[2];
    const float* W1   = (const float*)d_in[3];
    const float* b1   = (const float*)d_in[4];
    const float* W2   = (const float*)d_in[5];
    const float* b2   = (const float*)d_in[6];
    float* out = (float*)d_out;

    gemm_partial_kernel<<<dim3(24, KSPLIT), 256>>>(E, W1);
    fold_kernel<<<NN_ / 16, dim3(16, 16)>>>(pos, prev, W1, b1);
    pair_kernel<<<dim3(48, 48), dim3(16, 16)>>>(W1, W2, b2, out);
}

// round 8
// speedup vs baseline: 1.0010x; 1.0010x over previous
#include <cuda_runtime.h>
#include <math.h>

#define NN_ 1536
#define DD_ 768
#define HH_ 64
#define PLANE (NN_ * NN_)
#define KSPLIT 12

// Scratch (fully overwritten every launch -> graph-replay safe)
__device__ float g_part[KSPLIT * NN_ * 128]; // k-split partials of E@[W1a|W1b]
__device__ float g_A[NN_ * HH_];             // ha - g
__device__ float g_B[NN_ * HH_];             // hb + g + b1
__device__ float g_pv[NN_ * 6];              // pos(3), vel(3)

__device__ __forceinline__ void cpa16(unsigned s, const void* g) {
    asm volatile("cp.async.cg.shared.global [%0], [%1], 16;" :: "r"(s), "l"(g));
}
template <int N>
__device__ __forceinline__ void cp_wait() {
    asm volatile("cp.async.wait_group %0;" :: "n"(N) : "memory");
}

// ---------------------------------------------------------------------------
// Kernel 1: partial GEMM, 4-stage cp.async pipeline. grid (24, KSPLIT), 256t.
// Block (rb, ks): rows rb*64..+63, k-chunk ks*64..+63 (4 subtiles of 16),
// 128 output cols (0..63 = W1a, 64..127 = W1b). Per thread: 8 rows x 4 cols.
// All 4 subtile fills are issued up-front as separate commit groups; the
// compute loop waits them in completion order. One __syncthreads per subtile,
// no buffer reuse.
// ---------------------------------------------------------------------------
__global__ __launch_bounds__(256) void gemm_partial_kernel(
    const float* __restrict__ E, const float* __restrict__ W1)
{
    __shared__ __align__(16) float sE[4][64 * 16];   // [stage][row*16 + k] 4KB
    __shared__ __align__(16) float sW[4][16 * 128];  // [stage][kk*128 + h2] 8KB

    const int t    = threadIdx.x;
    const int rb   = blockIdx.x;
    const int ks   = blockIdx.y;
    const int lane = t & 31;   // col group: cols lane*4..+3
    const int wrp  = t >> 5;   // row group: rows wrp*8..+7

    // fill indices
    const int erow = t >> 2, ec4 = t & 3;   // E: 1 chunk (16B) per thread
    const int kk1  = t >> 5, q   = t & 31;  // W: 2 chunks per thread

    const unsigned se_b = (unsigned)__cvta_generic_to_shared(&sE[0][0]);
    const unsigned sw_b = (unsigned)__cvta_generic_to_shared(&sW[0][0]);

    // issue all 4 subtile fills (one commit group each)
#pragma unroll
    for (int kt = 0; kt < 4; ++kt) {
        const int kb = ks * 64 + kt * 16;
        cpa16(se_b + (kt * 1024 + erow * 16 + ec4 * 4) * 4,
              E + (size_t)(rb * 64 + erow) * DD_ + kb + ec4 * 4);
        const float* gw0 = (q < 16) ? W1 + (kb + kk1) * 64 + q * 4
                                    : W1 + (DD_ + kb + kk1) * 64 + (q - 16) * 4;
        cpa16(sw_b + (kt * 2048 + kk1 * 128 + q * 4) * 4, gw0);
        const float* gw1 = (q < 16) ? W1 + (kb + kk1 + 8) * 64 + q * 4
                                    : W1 + (DD_ + kb + kk1 + 8) * 64 + (q - 16) * 4;
        cpa16(sw_b + (kt * 2048 + (kk1 + 8) * 128 + q * 4) * 4, gw1);
        asm volatile("cp.async.commit_group;" ::: "memory");
    }

    float4 acc[8];
#pragma unroll
    for (int r = 0; r < 8; ++r) acc[r] = make_float4(0.f, 0.f, 0.f, 0.f);

#pragma unroll
    for (int kt = 0; kt < 4; ++kt) {
        if (kt == 0)      cp_wait<3>();
        else if (kt == 1) cp_wait<2>();
        else if (kt == 2) cp_wait<1>();
        else              cp_wait<0>();
        __syncthreads();

        const float4* sW4 = reinterpret_cast<const float4*>(sW[kt]);
        const float4* sE4 = reinterpret_cast<const float4*>(sE[kt]);
#pragma unroll
        for (int k4 = 0; k4 < 4; ++k4) {
            float4 w0 = sW4[(k4 * 4 + 0) * 32 + lane];
            float4 w1 = sW4[(k4 * 4 + 1) * 32 + lane];
            float4 w2 = sW4[(k4 * 4 + 2) * 32 + lane];
            float4 w3 = sW4[(k4 * 4 + 3) * 32 + lane];
#pragma unroll
            for (int r = 0; r < 8; ++r) {
                float4 e = sE4[(wrp * 8 + r) * 4 + k4];  // k-values k4*4..+3
                acc[r].x = fmaf(e.x, w0.x, acc[r].x);
                acc[r].y = fmaf(e.x, w0.y, acc[r].y);
                acc[r].z = fmaf(e.x, w0.z, acc[r].z);
                acc[r].w = fmaf(e.x, w0.w, acc[r].w);
                acc[r].x = fmaf(e.y, w1.x, acc[r].x);
                acc[r].y = fmaf(e.y, w1.y, acc[r].y);
                acc[r].z = fmaf(e.y, w1.z, acc[r].z);
                acc[r].w = fmaf(e.y, w1.w, acc[r].w);
                acc[r].x = fmaf(e.z, w2.x, acc[r].x);
                acc[r].y = fmaf(e.z, w2.y, acc[r].y);
                acc[r].z = fmaf(e.z, w2.z, acc[r].z);
                acc[r].w = fmaf(e.z, w2.w, acc[r].w);
                acc[r].x = fmaf(e.w, w3.x, acc[r].x);
                acc[r].y = fmaf(e.w, w3.y, acc[r].y);
                acc[r].z = fmaf(e.w, w3.z, acc[r].z);
                acc[r].w = fmaf(e.w, w3.w, acc[r].w);
            }
        }
    }

    float4* dst = reinterpret_cast<float4*>(g_part) + (size_t)ks * (NN_ * 32);
    const int rbase = rb * 64 + wrp * 8;
#pragma unroll
    for (int r = 0; r < 8; ++r)
        dst[(rbase + r) * 32 + lane] = acc[r];
}

// ---------------------------------------------------------------------------
// Kernel 2: reduce partials + fold geometry. grid 96, block (16,16).
// Thread (h4, i_local): float4 over the h dimension, 24 independent LDG.128.
// ---------------------------------------------------------------------------
__global__ __launch_bounds__(256) void fold_kernel(
    const float* __restrict__ pos, const float* __restrict__ prev,
    const float* __restrict__ W1, const float* __restrict__ b1)
{
    const int h4 = threadIdx.x;                     // 0..15
    const int i  = blockIdx.x * 16 + threadIdx.y;

    const float4* P4 = reinterpret_cast<const float4*>(g_part);
    float4 sa = make_float4(0.f, 0.f, 0.f, 0.f);
    float4 sb = make_float4(0.f, 0.f, 0.f, 0.f);
#pragma unroll
    for (int s = 0; s < KSPLIT; ++s) {
        size_t base = ((size_t)s * (NN_ * 128) + (size_t)i * 128) >> 2;
        float4 va = P4[base + h4];
        float4 vb = P4[base + 16 + h4];
        sa.x += va.x; sa.y += va.y; sa.z += va.z; sa.w += va.w;
        sb.x += vb.x; sb.y += vb.y; sb.z += vb.z; sb.w += vb.w;
    }

    float px = pos[i * 3 + 0], py = pos[i * 3 + 1], pz = pos[i * 3 + 2];
    float vx = px - prev[i * 3 + 0];
    float vy = py - prev[i * 3 + 1];
    float vz = pz - prev[i * 3 + 2];

    const float4* Ws4 = reinterpret_cast<const float4*>(W1 + 2 * DD_ * 64);
    float4 w0 = Ws4[0 * 16 + h4], w1 = Ws4[1 * 16 + h4], w2 = Ws4[2 * 16 + h4];
    float4 w4 = Ws4[4 * 16 + h4], w5 = Ws4[5 * 16 + h4], w6 = Ws4[6 * 16 + h4];
    float4 w7 = Ws4[7 * 16 + h4];
    float4 b14 = reinterpret_cast<const float4*>(b1)[h4];

    float4 g;
    g.x = px*w0.x + py*w1.x + pz*w2.x + vx*w4.x + vy*w5.x + vz*w6.x + py*w7.x;
    g.y = px*w0.y + py*w1.y + pz*w2.y + vx*w4.y + vy*w5.y + vz*w6.y + py*w7.y;
    g.z = px*w0.z + py*w1.z + pz*w2.z + vx*w4.z + vy*w5.z + vz*w6.z + py*w7.z;
    g.w = px*w0.w + py*w1.w + pz*w2.w + vx*w4.w + vy*w5.w + vz*w6.w + py*w7.w;

    float4 outA = make_float4(sa.x - g.x, sa.y - g.y, sa.z - g.z, sa.w - g.w);
    float4 outB = make_float4(sb.x + g.x + b14.x, sb.y + g.y + b14.y,
                              sb.z + g.z + b14.z, sb.w + g.w + b14.w);
    reinterpret_cast<float4*>(g_A)[i * 16 + h4] = outA;
    reinterpret_cast<float4*>(g_B)[i * 16 + h4] = outB;

    if (h4 == 0) {
        g_pv[i * 6 + 0] = px; g_pv[i * 6 + 1] = py; g_pv[i * 6 + 2] = pz;
        g_pv[i * 6 + 3] = vx; g_pv[i * 6 + 4] = vy; g_pv[i * 6 + 5] = vz;
    }
}

// ---------------------------------------------------------------------------
// Kernel 3: pairwise. grid (48, 48), block (16, 16). Each thread: 2x2 strided
// micro-tile i in {ty, ty+16}, j in {tx, tx+16}.
// Logits as softmax-invariant differences: delta_k = l_k - l_0 using
// W2d[h][k] = W2[h][k+1] - W2[h][0]  (3 accumulators per pair, not 4).
// ---------------------------------------------------------------------------
__global__ __launch_bounds__(256) void pair_kernel(
    const float* __restrict__ W1, const float* __restrict__ W2,
    const float* __restrict__ b2, float* __restrict__ out)
{
    __shared__ __align__(16) float sA[32 * 68];   // rows padded to 68 floats
    __shared__ __align__(16) float sB[32 * 68];
    __shared__ __align__(16) float4 sW2d[64];     // (d1,d2,d3,0) per h
    __shared__ __align__(16) float sW3[64];
    __shared__ float sPVi[32 * 6];
    __shared__ float sPVj[32 * 6];

    const int tx = threadIdx.x, ty = threadIdx.y;
    const int t  = ty * 16 + tx;
    const int i0 = blockIdx.y * 32;
    const int j0 = blockIdx.x * 32;

    for (int idx = t; idx < 512; idx += 256) {
        int r = idx >> 4, c = idx & 15;
        reinterpret_cast<float4*>(sA)[r * 17 + c] =
            reinterpret_cast<const float4*>(g_A)[(i0 + r) * 16 + c];
        reinterpret_cast<float4*>(sB)[r * 17 + c] =
            reinterpret_cast<const float4*>(g_B)[(j0 + r) * 16 + c];
    }
    if (t < 64) {
        float w0 = W2[t * 4 + 0];
        sW2d[t] = make_float4(W2[t * 4 + 1] - w0, W2[t * 4 + 2] - w0,
                              W2[t * 4 + 3] - w0, 0.f);
        sW3[t] = W1[(2 * DD_ + 3) * 64 + t];  // w3 = W1s row 3 (distance)
    }
    for (int idx = t; idx < 192; idx += 256) {
        sPVi[idx] = g_pv[i0 * 6 + idx];
        sPVj[idx] = g_pv[j0 * 6 + idx];
    }
    __syncthreads();

    // geometry for the 4 pairs
    float dist[4], clos[4], vdif[4];
#pragma unroll
    for (int p = 0; p < 2; ++p) {
        int ri = ty + p * 16;
        float pix = sPVi[ri * 6 + 0], piy = sPVi[ri * 6 + 1], piz = sPVi[ri * 6 + 2];
        float vix = sPVi[ri * 6 + 3], viy = sPVi[ri * 6 + 4], viz = sPVi[ri * 6 + 5];
#pragma unroll
        for (int q = 0; q < 2; ++q) {
            int rj = tx + q * 16;
            float rpx = sPVj[rj * 6 + 0] - pix;
            float rpy = sPVj[rj * 6 + 1] - piy;
            float rpz = sPVj[rj * 6 + 2] - piz;
            float rvx = sPVj[rj * 6 + 3] - vix;
            float rvy = sPVj[rj * 6 + 4] - viy;
            float rvz = sPVj[rj * 6 + 5] - viz;
            float d = sqrtf(rpx * rpx + rpy * rpy + rpz * rpz);
            float dot = rpx * rvx + rpy * rvy + rpz * rvz;
            int pq = p * 2 + q;
            dist[pq] = d;
            clos[pq] = -dot / fmaxf(d, 1e-6f);
            vdif[pq] = rpy;
        }
    }

    float acc1[4] = {0.f, 0.f, 0.f, 0.f};
    float acc2[4] = {0.f, 0.f, 0.f, 0.f};
    float acc3[4] = {0.f, 0.f, 0.f, 0.f};

    const float4* A4  = reinterpret_cast<const float4*>(sA);
    const float4* B4  = reinterpret_cast<const float4*>(sB);
    const float4* W34 = reinterpret_cast<const float4*>(sW3);

#pragma unroll 4
    for (int h4 = 0; h4 < 16; ++h4) {
        float4 af[2], bf[2];
        af[0] = A4[ty * 17 + h4];
        af[1] = A4[(ty + 16) * 17 + h4];
        bf[0] = B4[tx * 17 + h4];
        bf[1] = B4[(tx + 16) * 17 + h4];
        float4 w3v = W34[h4];
        float4 wd0 = sW2d[h4 * 4 + 0];
        float4 wd1 = sW2d[h4 * 4 + 1];
        float4 wd2 = sW2d[h4 * 4 + 2];
        float4 wd3 = sW2d[h4 * 4 + 3];

        const float aw[2][4] = {{af[0].x, af[0].y, af[0].z, af[0].w},
                                {af[1].x, af[1].y, af[1].z, af[1].w}};
        const float bw[2][4] = {{bf[0].x, bf[0].y, bf[0].z, bf[0].w},
                                {bf[1].x, bf[1].y, bf[1].z, bf[1].w}};
        const float w3a[4] = {w3v.x, w3v.y, w3v.z, w3v.w};
        const float4 wda[4] = {wd0, wd1, wd2, wd3};

#pragma unroll
        for (int hh = 0; hh < 4; ++hh) {
            const float w3h = w3a[hh];
            const float4 wd = wda[hh];
#pragma unroll
            for (int p = 0; p < 2; ++p) {
#pragma unroll
                for (int q = 0; q < 2; ++q) {
                    const int pq = p * 2 + q;
                    float tt = fmaf(dist[pq], w3h, aw[p][hh] + bw[q][hh]);
                    float r  = fmaxf(tt, 0.f);
                    acc1[pq] = fmaf(r, wd.x, acc1[pq]);
                    acc2[pq] = fmaf(r, wd.y, acc2[pq]);
                    acc3[pq] = fmaf(r, wd.z, acc3[pq]);
                }
            }
        }
    }

    const float db1 = __ldg(&b2[1]) - __ldg(&b2[0]);
    const float db2 = __ldg(&b2[2]) - __ldg(&b2[0]);
    const float db3 = __ldg(&b2[3]) - __ldg(&b2[0]);

#pragma unroll
    for (int p = 0; p < 2; ++p) {
#pragma unroll
        for (int q = 0; q < 2; ++q) {
            const int pq = p * 2 + q;
            float d1 = acc1[pq] + db1;
            float d2 = acc2[pq] + db2;
            float d3 = acc3[pq] + db3;
            float m = fmaxf(fmaxf(0.f, d1), fmaxf(d2, d3));
            float sum = __expf(0.f - m) + __expf(d1 - m)
                      + __expf(d2 - m) + __expf(d3 - m);
            float conf = __fdividef(1.0f, sum);
            int best = 0; float bm = 0.f;
            if (d1 > bm) { bm = d1; best = 1; }
            if (d2 > bm) { bm = d2; best = 2; }
            if (d3 > bm) { bm = d3; best = 3; }

            float d = dist[pq], c = clos[pq], v = vdif[pq];
            bool near  = d < 0.25f;
            bool appr  = !near && (c > 0.05f);
            bool flee  = !near && !appr && (c < -0.05f);
            bool above = !near && !appr && !flee && (fabsf(v) > 0.3f) && (d < 0.5f);

            int rt = near ? 0 : (appr ? 1 : (flee ? 2 : (above ? 3 : best)));
            float co = conf;
            if (near)              co = fmaxf(co, 0.8f);
            else if (appr || flee) co = fmaxf(co, 0.6f);
            else if (above)        co = fmaxf(co, 0.5f);

            int ig = i0 + ty + p * 16;
            int jg = j0 + tx + q * 16;
            size_t off = (size_t)ig * NN_ + jg;
            out[off]             = (float)rt;
            out[PLANE + off]     = co;
            out[2 * PLANE + off] = (jg > ig && co > 0.3f) ? 1.0f : 0.0f;
        }
    }
}

extern "C" void kernel_launch(void* const* d_in, const int* in_sizes, int n_in,
                              void* d_out, int out_size)
{
    const float* E    = (const float*)d_in[0];
    const float* pos  = (const float*)d_in[1];
    const float* prev = (const float*)d_in[2];
    const float* W1   = (const float*)d_in[3];
    const float* b1   = (const float*)d_in[4];
    const float* W2   = (const float*)d_in[5];
    const float* b2   = (const float*)d_in[6];
    float* out = (float*)d_out;

    gemm_partial_kernel<<<dim3(24, KSPLIT), 256>>>(E, W1);
    fold_kernel<<<NN_ / 16, dim3(16, 16)>>>(pos, prev, W1, b1);
    pair_kernel<<<dim3(48, 48), dim3(16, 16)>>>(W1, W2, b2, out);
}